// round 6
// baseline (speedup 1.0000x reference)
#include <cuda_runtime.h>
#include <math.h>

// DistinctionLoss fused single-kernel, high-occupancy version.
// features [8,4096,256] f32, scores [8,4096,1] f32 -> scalar f32.
//
// mean(gram) = sum_b ||s_b||^2 / (B*N^2), s_b = sum_n unit(features[b,n,:]).
// One persistent kernel: phase1 (norms + s_b accum) -> grid barrier ->
// phase2 (per-row dot vs s_b, BCE) -> grid barrier -> block 0 finalize+reset.
// 128 blocks x 1024 threads: 32 warps/SM (50% occ) to hide load/shuffle latency.

#define BB 8
#define NN 4096
#define DD 256
#define NBLK 128
#define NTHREADS 1024
#define NWARPS (NTHREADS / 32)                   // 32
#define ROWS_PER_BLOCK ((BB * NN) / NBLK)        // 256
#define ROWS_PER_WARP  (ROWS_PER_BLOCK / NWARPS) // 8
#define RBATCH 2

// Persistent scratch; zero-initialized at module load, self-reset each launch.
__device__ float  g_s[BB * DD];
__device__ double g_bce;
__device__ unsigned int g_count;
__device__ volatile unsigned int g_gen;

__device__ __forceinline__ void grid_barrier() {
    __syncthreads();
    if (threadIdx.x == 0) {
        __threadfence();                    // publish this block's writes
        unsigned int gen = g_gen;           // read phase BEFORE arriving
        if (atomicAdd(&g_count, 1u) == NBLK - 1) {
            g_count = 0;
            __threadfence();
            g_gen = gen + 1;                // release
        } else {
            while (g_gen == gen) __nanosleep(32);
        }
    }
    __syncthreads();
}

__global__ void __launch_bounds__(NTHREADS, 1) fused_kernel(
        const float* __restrict__ feat,
        const float* __restrict__ scores,
        float* __restrict__ out) {
    __shared__ float s_acc[DD];
    __shared__ float s_vec[DD];
    __shared__ float s_rn[ROWS_PER_BLOCK];
    __shared__ float s_red[NWARPS];
    __shared__ float s_fin[NWARPS];

    int tid  = threadIdx.x;
    int wid  = tid >> 5;
    int lane = tid & 31;

    int rowBase = blockIdx.x * ROWS_PER_BLOCK;   // 256 | 4096 -> single batch
    int b       = rowBase / NN;
    int row0    = rowBase + wid * ROWS_PER_WARP;

    if (tid < DD) s_acc[tid] = 0.0f;
    __syncthreads();

    // ---------------- Phase 1: row norms + s_b accumulation ----------------
    float4 acc0 = make_float4(0.f, 0.f, 0.f, 0.f);
    float4 acc1 = make_float4(0.f, 0.f, 0.f, 0.f);

    #pragma unroll
    for (int rb = 0; rb < ROWS_PER_WARP; rb += RBATCH) {
        float4 a0[RBATCH], a1[RBATCH];
        #pragma unroll
        for (int r = 0; r < RBATCH; r++) {        // independent LDG.128s
            const float4* p = (const float4*)(feat + (size_t)(row0 + rb + r) * DD);
            a0[r] = p[lane];
            a1[r] = p[lane + 32];
        }
        float ss[RBATCH];
        #pragma unroll
        for (int r = 0; r < RBATCH; r++)
            ss[r] = a0[r].x*a0[r].x + a0[r].y*a0[r].y + a0[r].z*a0[r].z + a0[r].w*a0[r].w
                  + a1[r].x*a1[r].x + a1[r].y*a1[r].y + a1[r].z*a1[r].z + a1[r].w*a1[r].w;
        #pragma unroll
        for (int o = 16; o > 0; o >>= 1) {        // interleaved butterflies
            #pragma unroll
            for (int r = 0; r < RBATCH; r++)
                ss[r] += __shfl_xor_sync(0xffffffffu, ss[r], o);
        }
        #pragma unroll
        for (int r = 0; r < RBATCH; r++) {
            float rn_ = rsqrtf(fmaxf(ss[r], 1e-24f));
            if (lane == 0) s_rn[wid * ROWS_PER_WARP + rb + r] = rn_;
            acc0.x += a0[r].x * rn_; acc0.y += a0[r].y * rn_;
            acc0.z += a0[r].z * rn_; acc0.w += a0[r].w * rn_;
            acc1.x += a1[r].x * rn_; acc1.y += a1[r].y * rn_;
            acc1.z += a1[r].z * rn_; acc1.w += a1[r].w * rn_;
        }
    }

    int d0 = lane * 4;
    atomicAdd(&s_acc[d0 + 0],       acc0.x);
    atomicAdd(&s_acc[d0 + 1],       acc0.y);
    atomicAdd(&s_acc[d0 + 2],       acc0.z);
    atomicAdd(&s_acc[d0 + 3],       acc0.w);
    atomicAdd(&s_acc[128 + d0 + 0], acc1.x);
    atomicAdd(&s_acc[128 + d0 + 1], acc1.y);
    atomicAdd(&s_acc[128 + d0 + 2], acc1.z);
    atomicAdd(&s_acc[128 + d0 + 3], acc1.w);
    __syncthreads();

    if (tid < DD) atomicAdd(&g_s[b * DD + tid], s_acc[tid]);

    grid_barrier();

    // ---------------- Phase 2: per-row dot with s_b -> BCE ----------------
    if (tid < DD) s_vec[tid] = __ldcg(&g_s[b * DD + tid]); // atomics landed in L2
    __syncthreads();

    const float4* sv = (const float4*)s_vec;
    float4 s0 = sv[lane];
    float4 s1 = sv[lane + 32];

    float local = 0.0f;
    #pragma unroll
    for (int rb = 0; rb < ROWS_PER_WARP; rb += RBATCH) {
        float4 a0[RBATCH], a1[RBATCH];
        #pragma unroll
        for (int r = 0; r < RBATCH; r++) {
            const float4* p = (const float4*)(feat + (size_t)(row0 + rb + r) * DD);
            a0[r] = p[lane];
            a1[r] = p[lane + 32];
        }
        float dt[RBATCH];
        #pragma unroll
        for (int r = 0; r < RBATCH; r++)
            dt[r] = a0[r].x*s0.x + a0[r].y*s0.y + a0[r].z*s0.z + a0[r].w*s0.w
                  + a1[r].x*s1.x + a1[r].y*s1.y + a1[r].z*s1.z + a1[r].w*s1.w;
        #pragma unroll
        for (int o = 16; o > 0; o >>= 1) {
            #pragma unroll
            for (int r = 0; r < RBATCH; r++)
                dt[r] += __shfl_xor_sync(0xffffffffu, dt[r], o);
        }
        if (lane == 0) {
            #pragma unroll
            for (int r = 0; r < RBATCH; r++) {
                int row = row0 + rb + r;
                float fs  = dt[r] * s_rn[wid * ROWS_PER_WARP + rb + r];
                float sim = (fs - 1.0f) * (1.0f / (float)(NN - 1));
                float t   = 1.0f - fmaxf(sim, 0.0f);
                float sc  = scores[row];
                float ls  = fmaxf(logf(sc),    -100.0f);
                float l1  = fmaxf(log1pf(-sc), -100.0f);
                local += -(t * ls + (1.0f - t) * l1);
            }
        }
    }

    if (lane == 0) s_red[wid] = local;
    __syncthreads();
    if (wid == 0) {                      // warp 0 reduces the 32 warp partials
        float sum = s_red[lane];
        #pragma unroll
        for (int o = 16; o > 0; o >>= 1)
            sum += __shfl_xor_sync(0xffffffffu, sum, o);
        if (lane == 0) atomicAdd(&g_bce, (double)sum);
    }

    grid_barrier();

    // ---------------- Finalize + reset (block 0 only) ----------------
    if (blockIdx.x == 0) {
        float ss = 0.0f;
        #pragma unroll
        for (int i = 0; i < (BB * DD) / NTHREADS; i++) {
            float v = __ldcg(&g_s[tid + i * NTHREADS]);
            ss += v * v;
        }
        #pragma unroll
        for (int o = 16; o > 0; o >>= 1)
            ss += __shfl_xor_sync(0xffffffffu, ss, o);
        if (lane == 0) s_fin[wid] = ss;
        __syncthreads();
        if (wid == 0) {
            float t = s_fin[lane];
            #pragma unroll
            for (int o = 16; o > 0; o >>= 1)
                t += __shfl_xor_sync(0xffffffffu, t, o);
            if (lane == 0) {
                double bce       = atomicAdd(&g_bce, 0.0) / (double)(BB * NN);
                double mean_gram = (double)t /
                                   ((double)BB * (double)NN * (double)NN);
                out[0] = (float)(bce + (1.0 - mean_gram));
                g_bce = 0.0;                               // reset for next launch
            }
        }
        __syncthreads();                                   // all reads of g_s done
        #pragma unroll
        for (int i = 0; i < (BB * DD) / NTHREADS; i++)
            g_s[tid + i * NTHREADS] = 0.0f;                // reset for next launch
    }
}

extern "C" void kernel_launch(void* const* d_in, const int* in_sizes, int n_in,
                              void* d_out, int out_size) {
    const float* feat   = (const float*)d_in[0];
    const float* scores = (const float*)d_in[1];
    float* out = (float*)d_out;

    fused_kernel<<<NBLK, NTHREADS>>>(feat, scores, out);
}

// round 8
// speedup vs baseline: 1.0014x; 1.0014x over previous
#include <cuda_runtime.h>
#include <cuda_bf16.h>
#include <math.h>

// DistinctionLoss fused single-kernel, register-cached version (proven barriers).
// features [8,4096,256] f32, scores [8,4096,1] f32 -> scalar f32.
//
// mean(gram) = sum_b ||s_b||^2 / (B*N^2), s_b = sum_n unit(features[b,n,:]).
// Phase 1 streams features once from HBM, computes row norms, accumulates s_b,
// and caches each normalized row in REGISTERS as bf16 (4 x bf16x2 per lane per
// row). Phase 2 is pure ALU: dot(cached unit row, s_b) -> target -> BCE.

#define BB 8
#define NN 4096
#define DD 256
#define NBLK 128
#define NTHREADS 512
#define NWARPS (NTHREADS / 32)                   // 16
#define ROWS_PER_BLOCK ((BB * NN) / NBLK)        // 256
#define ROWS_PER_WARP  (ROWS_PER_BLOCK / NWARPS) // 16
#define RBATCH 4

// Persistent scratch; zero-initialized at module load, self-reset each launch.
__device__ float  g_s[BB * DD];
__device__ double g_bce;
__device__ unsigned int g_count;
__device__ volatile unsigned int g_gen;

__device__ __forceinline__ void grid_barrier() {
    __syncthreads();
    if (threadIdx.x == 0) {
        __threadfence();                    // publish this block's writes
        unsigned int gen = g_gen;           // read phase BEFORE arriving
        if (atomicAdd(&g_count, 1u) == NBLK - 1) {
            g_count = 0;
            __threadfence();
            g_gen = gen + 1;                // release
        } else {
            while (g_gen == gen) __nanosleep(32);
        }
    }
    __syncthreads();
}

__global__ void __launch_bounds__(NTHREADS, 1) fused_kernel(
        const float* __restrict__ feat,
        const float* __restrict__ scores,
        float* __restrict__ out) {
    __shared__ float s_acc[DD];
    __shared__ float s_red[NWARPS];

    int tid  = threadIdx.x;
    int wid  = tid >> 5;
    int lane = tid & 31;

    int rowBase = blockIdx.x * ROWS_PER_BLOCK;   // 256 | 4096 -> single batch
    int b       = rowBase / NN;
    int row0    = rowBase + wid * ROWS_PER_WARP;

    if (tid < DD) s_acc[tid] = 0.0f;
    __syncthreads();

    // ---------------- Phase 1: norms + s_b accum + bf16 register cache -----
    __nv_bfloat162 c0[ROWS_PER_WARP], c1[ROWS_PER_WARP];
    __nv_bfloat162 c2[ROWS_PER_WARP], c3[ROWS_PER_WARP];
    float4 acc0 = make_float4(0.f, 0.f, 0.f, 0.f);
    float4 acc1 = make_float4(0.f, 0.f, 0.f, 0.f);

    #pragma unroll
    for (int rb = 0; rb < ROWS_PER_WARP; rb += RBATCH) {
        float4 a0[RBATCH], a1[RBATCH];
        #pragma unroll
        for (int r = 0; r < RBATCH; r++) {        // 8 independent LDG.128
            const float4* p = (const float4*)(feat + (size_t)(row0 + rb + r) * DD);
            a0[r] = p[lane];
            a1[r] = p[lane + 32];
        }
        float ss[RBATCH];
        #pragma unroll
        for (int r = 0; r < RBATCH; r++)
            ss[r] = a0[r].x*a0[r].x + a0[r].y*a0[r].y + a0[r].z*a0[r].z + a0[r].w*a0[r].w
                  + a1[r].x*a1[r].x + a1[r].y*a1[r].y + a1[r].z*a1[r].z + a1[r].w*a1[r].w;
        #pragma unroll
        for (int o = 16; o > 0; o >>= 1) {        // 4 interleaved butterflies
            #pragma unroll
            for (int r = 0; r < RBATCH; r++)
                ss[r] += __shfl_xor_sync(0xffffffffu, ss[r], o);
        }
        #pragma unroll
        for (int r = 0; r < RBATCH; r++) {
            float rn_ = rsqrtf(fmaxf(ss[r], 1e-24f));
            float4 u0, u1;
            u0.x = a0[r].x * rn_; u0.y = a0[r].y * rn_;
            u0.z = a0[r].z * rn_; u0.w = a0[r].w * rn_;
            u1.x = a1[r].x * rn_; u1.y = a1[r].y * rn_;
            u1.z = a1[r].z * rn_; u1.w = a1[r].w * rn_;
            acc0.x += u0.x; acc0.y += u0.y; acc0.z += u0.z; acc0.w += u0.w;
            acc1.x += u1.x; acc1.y += u1.y; acc1.z += u1.z; acc1.w += u1.w;
            c0[rb + r] = __float22bfloat162_rn(make_float2(u0.x, u0.y));
            c1[rb + r] = __float22bfloat162_rn(make_float2(u0.z, u0.w));
            c2[rb + r] = __float22bfloat162_rn(make_float2(u1.x, u1.y));
            c3[rb + r] = __float22bfloat162_rn(make_float2(u1.z, u1.w));
        }
    }

    int d0 = lane * 4;
    atomicAdd(&s_acc[d0 + 0],       acc0.x);
    atomicAdd(&s_acc[d0 + 1],       acc0.y);
    atomicAdd(&s_acc[d0 + 2],       acc0.z);
    atomicAdd(&s_acc[d0 + 3],       acc0.w);
    atomicAdd(&s_acc[128 + d0 + 0], acc1.x);
    atomicAdd(&s_acc[128 + d0 + 1], acc1.y);
    atomicAdd(&s_acc[128 + d0 + 2], acc1.z);
    atomicAdd(&s_acc[128 + d0 + 3], acc1.w);
    __syncthreads();

    if (tid < DD) atomicAdd(&g_s[b * DD + tid], s_acc[tid]);

    grid_barrier();

    // ---------------- Phase 2: pure-ALU dot with s_b -> BCE ----------------
    // Lane-mapped s_b slices straight from L2 (atomics landed there).
    const float4* gs4 = (const float4*)(g_s + b * DD);
    float4 s0 = __ldcg(&gs4[lane]);
    float4 s1 = __ldcg(&gs4[lane + 32]);

    float local = 0.0f;
    #pragma unroll
    for (int rb = 0; rb < ROWS_PER_WARP; rb += RBATCH) {
        float dt[RBATCH];
        #pragma unroll
        for (int r = 0; r < RBATCH; r++) {
            float2 f0 = __bfloat1622float2(c0[rb + r]);
            float2 f1 = __bfloat1622float2(c1[rb + r]);
            float2 f2 = __bfloat1622float2(c2[rb + r]);
            float2 f3 = __bfloat1622float2(c3[rb + r]);
            dt[r] = f0.x*s0.x + f0.y*s0.y + f1.x*s0.z + f1.y*s0.w
                  + f2.x*s1.x + f2.y*s1.y + f3.x*s1.z + f3.y*s1.w;
        }
        #pragma unroll
        for (int o = 16; o > 0; o >>= 1) {
            #pragma unroll
            for (int r = 0; r < RBATCH; r++)
                dt[r] += __shfl_xor_sync(0xffffffffu, dt[r], o);
        }
        if (lane == 0) {
            #pragma unroll
            for (int r = 0; r < RBATCH; r++) {
                int row = row0 + rb + r;
                float fs  = dt[r];                             // unit-row . s_b
                float sim = (fs - 1.0f) * (1.0f / (float)(NN - 1));
                float t   = 1.0f - fmaxf(sim, 0.0f);
                float sc  = scores[row];
                float ls  = fmaxf(logf(sc),    -100.0f);
                float l1  = fmaxf(log1pf(-sc), -100.0f);
                local += -(t * ls + (1.0f - t) * l1);
            }
        }
    }

    if (lane == 0) s_red[wid] = local;
    __syncthreads();
    if (tid == 0) {
        float sum = 0.0f;
        #pragma unroll
        for (int i = 0; i < NWARPS; i++) sum += s_red[i];
        atomicAdd(&g_bce, (double)sum);
    }

    grid_barrier();

    // ---------------- Finalize + reset (block 0 only) ----------------
    if (blockIdx.x == 0) {
        float ss = 0.0f;
        #pragma unroll
        for (int i = 0; i < (BB * DD) / NTHREADS; i++) {
            float v = __ldcg(&g_s[tid + i * NTHREADS]);
            ss += v * v;
        }
        #pragma unroll
        for (int o = 16; o > 0; o >>= 1)
            ss += __shfl_xor_sync(0xffffffffu, ss, o);
        if (lane == 0) s_red[wid] = ss;
        __syncthreads();
        if (wid == 0) {
            float t = (lane < NWARPS) ? s_red[lane] : 0.0f;
            #pragma unroll
            for (int o = 8; o > 0; o >>= 1)
                t += __shfl_xor_sync(0xffffffffu, t, o);
            if (lane == 0) {
                double bce       = atomicAdd(&g_bce, 0.0) / (double)(BB * NN);
                double mean_gram = (double)t /
                                   ((double)BB * (double)NN * (double)NN);
                out[0] = (float)(bce + (1.0 - mean_gram));
                g_bce = 0.0;                     // reset for next launch
            }
        }
        __syncthreads();                         // all reads of g_s done
        #pragma unroll
        for (int i = 0; i < (BB * DD) / NTHREADS; i++)
            g_s[tid + i * NTHREADS] = 0.0f;      // reset for next launch
    }
}

extern "C" void kernel_launch(void* const* d_in, const int* in_sizes, int n_in,
                              void* d_out, int out_size) {
    const float* feat   = (const float*)d_in[0];
    const float* scores = (const float*)d_in[1];
    float* out = (float*)d_out;

    fused_kernel<<<NBLK, NTHREADS>>>(feat, scores, out);
}

// round 9
// speedup vs baseline: 1.1033x; 1.1017x over previous
#include <cuda_runtime.h>
#include <math.h>

// DistinctionLoss fused single-kernel, low-register / high-block-count version.
// features [8,4096,256] f32, scores [8,4096,1] f32 -> scalar f32.
//
// mean(gram) = sum_b ||s_b||^2 / (B*N^2), s_b = sum_n unit(features[b,n,:]).
// Phase1 (norms + s_b accum) -> grid barrier -> phase2 (dot vs s_b, BCE)
// -> grid barrier -> block 0 finalize + state reset.
// 512 blocks x 256 threads, launch_bounds(256,4): regs <= 64 (no spills),
// 4 blocks/SM co-resident (grid barrier safe), 32 warps/SM.

#define BB 8
#define NN 4096
#define DD 256
#define NBLK 512
#define NTHREADS 256
#define NWARPS (NTHREADS / 32)                   // 8
#define ROWS_PER_BLOCK ((BB * NN) / NBLK)        // 64
#define ROWS_PER_WARP  (ROWS_PER_BLOCK / NWARPS) // 8
#define RBATCH 2

// Persistent scratch; zero-initialized at module load, self-reset each launch.
__device__ float  g_s[BB * DD];
__device__ double g_bce;
__device__ unsigned int g_count;
__device__ volatile unsigned int g_gen;

__device__ __forceinline__ void grid_barrier() {
    __syncthreads();
    if (threadIdx.x == 0) {
        __threadfence();                    // publish this block's writes
        unsigned int gen = g_gen;           // read phase BEFORE arriving
        if (atomicAdd(&g_count, 1u) == NBLK - 1) {
            g_count = 0;
            __threadfence();
            g_gen = gen + 1;                // release
        } else {
            while (g_gen == gen) __nanosleep(32);
        }
    }
    __syncthreads();
}

__global__ void __launch_bounds__(NTHREADS, 4) fused_kernel(
        const float* __restrict__ feat,
        const float* __restrict__ scores,
        float* __restrict__ out) {
    __shared__ float s_acc[DD];
    __shared__ float s_rn[ROWS_PER_BLOCK];
    __shared__ float s_red[NWARPS];

    int tid  = threadIdx.x;
    int wid  = tid >> 5;
    int lane = tid & 31;

    int rowBase = blockIdx.x * ROWS_PER_BLOCK;   // 64 | 4096 -> single batch
    int b       = rowBase >> 12;                 // /NN
    int row0    = rowBase + wid * ROWS_PER_WARP;

    s_acc[tid] = 0.0f;
    __syncthreads();

    // ---------------- Phase 1: row norms + s_b accumulation ----------------
    float4 acc0 = make_float4(0.f, 0.f, 0.f, 0.f);
    float4 acc1 = make_float4(0.f, 0.f, 0.f, 0.f);

    #pragma unroll
    for (int rb = 0; rb < ROWS_PER_WARP; rb += RBATCH) {
        float4 a0[RBATCH], a1[RBATCH];
        #pragma unroll
        for (int r = 0; r < RBATCH; r++) {        // 4 independent LDG.128
            const float4* p = (const float4*)(feat + (size_t)(row0 + rb + r) * DD);
            a0[r] = p[lane];
            a1[r] = p[lane + 32];
        }
        float ss[RBATCH];
        #pragma unroll
        for (int r = 0; r < RBATCH; r++)
            ss[r] = a0[r].x*a0[r].x + a0[r].y*a0[r].y + a0[r].z*a0[r].z + a0[r].w*a0[r].w
                  + a1[r].x*a1[r].x + a1[r].y*a1[r].y + a1[r].z*a1[r].z + a1[r].w*a1[r].w;
        #pragma unroll
        for (int o = 16; o > 0; o >>= 1) {        // interleaved butterflies
            #pragma unroll
            for (int r = 0; r < RBATCH; r++)
                ss[r] += __shfl_xor_sync(0xffffffffu, ss[r], o);
        }
        #pragma unroll
        for (int r = 0; r < RBATCH; r++) {
            float rn_ = rsqrtf(fmaxf(ss[r], 1e-24f));
            if (lane == 0) s_rn[wid * ROWS_PER_WARP + rb + r] = rn_;
            acc0.x += a0[r].x * rn_; acc0.y += a0[r].y * rn_;
            acc0.z += a0[r].z * rn_; acc0.w += a0[r].w * rn_;
            acc1.x += a1[r].x * rn_; acc1.y += a1[r].y * rn_;
            acc1.z += a1[r].z * rn_; acc1.w += a1[r].w * rn_;
        }
    }

    int d0 = lane * 4;
    atomicAdd(&s_acc[d0 + 0],       acc0.x);
    atomicAdd(&s_acc[d0 + 1],       acc0.y);
    atomicAdd(&s_acc[d0 + 2],       acc0.z);
    atomicAdd(&s_acc[d0 + 3],       acc0.w);
    atomicAdd(&s_acc[128 + d0 + 0], acc1.x);
    atomicAdd(&s_acc[128 + d0 + 1], acc1.y);
    atomicAdd(&s_acc[128 + d0 + 2], acc1.z);
    atomicAdd(&s_acc[128 + d0 + 3], acc1.w);
    __syncthreads();

    atomicAdd(&g_s[b * DD + tid], s_acc[tid]);

    grid_barrier();

    // ---------------- Phase 2: per-row dot with s_b -> BCE ----------------
    // Lane-mapped s_b slices straight from L2 (atomics landed there).
    const float4* gs4 = (const float4*)(g_s + b * DD);
    float4 s0 = __ldcg(&gs4[lane]);
    float4 s1 = __ldcg(&gs4[lane + 32]);

    float local = 0.0f;
    #pragma unroll
    for (int rb = 0; rb < ROWS_PER_WARP; rb += RBATCH) {
        float4 a0[RBATCH], a1[RBATCH];
        #pragma unroll
        for (int r = 0; r < RBATCH; r++) {
            const float4* p = (const float4*)(feat + (size_t)(row0 + rb + r) * DD);
            a0[r] = p[lane];
            a1[r] = p[lane + 32];
        }
        float dt[RBATCH];
        #pragma unroll
        for (int r = 0; r < RBATCH; r++)
            dt[r] = a0[r].x*s0.x + a0[r].y*s0.y + a0[r].z*s0.z + a0[r].w*s0.w
                  + a1[r].x*s1.x + a1[r].y*s1.y + a1[r].z*s1.z + a1[r].w*s1.w;
        #pragma unroll
        for (int o = 16; o > 0; o >>= 1) {
            #pragma unroll
            for (int r = 0; r < RBATCH; r++)
                dt[r] += __shfl_xor_sync(0xffffffffu, dt[r], o);
        }
        if (lane == 0) {
            #pragma unroll
            for (int r = 0; r < RBATCH; r++) {
                int row = row0 + rb + r;
                float fs  = dt[r] * s_rn[wid * ROWS_PER_WARP + rb + r];
                float sim = (fs - 1.0f) * (1.0f / (float)(NN - 1));
                float t   = 1.0f - fmaxf(sim, 0.0f);
                float sc  = scores[row];
                float ls  = fmaxf(logf(sc),    -100.0f);
                float l1  = fmaxf(log1pf(-sc), -100.0f);
                local += -(t * ls + (1.0f - t) * l1);
            }
        }
    }

    if (lane == 0) s_red[wid] = local;
    __syncthreads();
    if (tid == 0) {
        float sum = 0.0f;
        #pragma unroll
        for (int i = 0; i < NWARPS; i++) sum += s_red[i];
        atomicAdd(&g_bce, (double)sum);
    }

    grid_barrier();

    // ---------------- Finalize + reset (block 0 only) ----------------
    if (blockIdx.x == 0) {
        float ss = 0.0f;
        #pragma unroll
        for (int i = 0; i < (BB * DD) / NTHREADS; i++) {
            float v = __ldcg(&g_s[tid + i * NTHREADS]);
            ss += v * v;
        }
        #pragma unroll
        for (int o = 16; o > 0; o >>= 1)
            ss += __shfl_xor_sync(0xffffffffu, ss, o);
        if (lane == 0) s_red[wid] = ss;
        __syncthreads();
        if (wid == 0) {
            float t = (lane < NWARPS) ? s_red[lane] : 0.0f;
            #pragma unroll
            for (int o = 4; o > 0; o >>= 1)
                t += __shfl_xor_sync(0xffffffffu, t, o);
            if (lane == 0) {
                double bce       = atomicAdd(&g_bce, 0.0) / (double)(BB * NN);
                double mean_gram = (double)t /
                                   ((double)BB * (double)NN * (double)NN);
                out[0] = (float)(bce + (1.0 - mean_gram));
                g_bce = 0.0;                     // reset for next launch
            }
        }
        __syncthreads();                         // all reads of g_s done
        #pragma unroll
        for (int i = 0; i < (BB * DD) / NTHREADS; i++)
            g_s[tid + i * NTHREADS] = 0.0f;      // reset for next launch
    }
}

extern "C" void kernel_launch(void* const* d_in, const int* in_sizes, int n_in,
                              void* d_out, int out_size) {
    const float* feat   = (const float*)d_in[0];
    const float* scores = (const float*)d_in[1];
    float* out = (float*)d_out;

    fused_kernel<<<NBLK, NTHREADS>>>(feat, scores, out);
}

// round 11
// speedup vs baseline: 1.1770x; 1.0668x over previous
#include <cuda_runtime.h>
#include <math.h>

// DistinctionLoss: two-kernel version (no in-kernel grid barrier).
// features [8,4096,256] f32, scores [8,4096,1] f32 -> scalar f32.
//
// mean(gram) = sum_b ||s_b||^2 / (B*N^2), s_b = sum_n unit(features[b,n,:]).
// Kernel 1: per-row 1/norm + s_b accumulation (smem -> global atomics).
// Kernel 2: per-row dot vs s_b -> BCE partials; LAST block (atomic ticket)
//           finalizes ||s_b||^2, combines, writes out, resets state.

#define BB 8
#define NN 4096
#define DD 256
#define NBLK 512
#define NTHREADS 256
#define NWARPS (NTHREADS / 32)                   // 8
#define ROWS_PER_BLOCK ((BB * NN) / NBLK)        // 64
#define ROWS_PER_WARP  (ROWS_PER_BLOCK / NWARPS) // 8

// Persistent scratch; zero-initialized at module load, self-reset each launch.
__device__ float  g_rnorm[BB * NN];
__device__ float  g_s[BB * DD];
__device__ double g_bce;
__device__ unsigned int g_ticket;

// ---------------- Kernel 1: row norms + s_b accumulation ----------------
__global__ void __launch_bounds__(NTHREADS) pass1_kernel(const float* __restrict__ feat) {
    __shared__ float s_acc[DD];
    int tid  = threadIdx.x;
    int wid  = tid >> 5;
    int lane = tid & 31;
    s_acc[tid] = 0.0f;
    __syncthreads();

    int rowBase = blockIdx.x * ROWS_PER_BLOCK;   // 64 | 4096 -> single batch
    int b       = rowBase >> 12;
    int row0    = rowBase + wid * ROWS_PER_WARP;

    float4 acc0 = make_float4(0.f, 0.f, 0.f, 0.f);
    float4 acc1 = make_float4(0.f, 0.f, 0.f, 0.f);

    #pragma unroll
    for (int r = 0; r < ROWS_PER_WARP; r++) {
        int row = row0 + r;
        const float4* p = (const float4*)(feat + (size_t)row * DD);
        float4 v0 = p[lane];
        float4 v1 = p[lane + 32];
        float ss = v0.x*v0.x + v0.y*v0.y + v0.z*v0.z + v0.w*v0.w
                 + v1.x*v1.x + v1.y*v1.y + v1.z*v1.z + v1.w*v1.w;
        #pragma unroll
        for (int o = 16; o > 0; o >>= 1)
            ss += __shfl_xor_sync(0xffffffffu, ss, o);
        float rn = rsqrtf(fmaxf(ss, 1e-24f));
        if (lane == 0) g_rnorm[row] = rn;
        acc0.x += v0.x * rn; acc0.y += v0.y * rn;
        acc0.z += v0.z * rn; acc0.w += v0.w * rn;
        acc1.x += v1.x * rn; acc1.y += v1.y * rn;
        acc1.z += v1.z * rn; acc1.w += v1.w * rn;
    }

    int d0 = lane * 4;
    atomicAdd(&s_acc[d0 + 0],       acc0.x);
    atomicAdd(&s_acc[d0 + 1],       acc0.y);
    atomicAdd(&s_acc[d0 + 2],       acc0.z);
    atomicAdd(&s_acc[d0 + 3],       acc0.w);
    atomicAdd(&s_acc[128 + d0 + 0], acc1.x);
    atomicAdd(&s_acc[128 + d0 + 1], acc1.y);
    atomicAdd(&s_acc[128 + d0 + 2], acc1.z);
    atomicAdd(&s_acc[128 + d0 + 3], acc1.w);
    __syncthreads();

    atomicAdd(&g_s[b * DD + tid], s_acc[tid]);
}

// -------- Kernel 2: dot vs s_b -> BCE; last block finalizes + resets --------
__global__ void __launch_bounds__(NTHREADS) pass2_kernel(const float* __restrict__ feat,
                                                         const float* __restrict__ scores,
                                                         float* __restrict__ out) {
    __shared__ float s_red[NWARPS];
    int tid  = threadIdx.x;
    int wid  = tid >> 5;
    int lane = tid & 31;

    int rowBase = blockIdx.x * ROWS_PER_BLOCK;
    int b       = rowBase >> 12;
    int row0    = rowBase + wid * ROWS_PER_WARP;

    // Lane-mapped s_b slices (atomics from pass1 landed in L2).
    const float4* gs4 = (const float4*)(g_s + b * DD);
    float4 s0 = __ldcg(&gs4[lane]);
    float4 s1 = __ldcg(&gs4[lane + 32]);

    float local = 0.0f;
    #pragma unroll
    for (int r = 0; r < ROWS_PER_WARP; r++) {
        int row = row0 + r;
        const float4* p = (const float4*)(feat + (size_t)row * DD);
        float4 v0 = p[lane];
        float4 v1 = p[lane + 32];
        float dot = v0.x*s0.x + v0.y*s0.y + v0.z*s0.z + v0.w*s0.w
                  + v1.x*s1.x + v1.y*s1.y + v1.z*s1.z + v1.w*s1.w;
        #pragma unroll
        for (int o = 16; o > 0; o >>= 1)
            dot += __shfl_xor_sync(0xffffffffu, dot, o);
        if (lane == 0) {
            float fs  = dot * g_rnorm[row];
            float sim = (fs - 1.0f) * (1.0f / (float)(NN - 1));
            float t   = 1.0f - fmaxf(sim, 0.0f);
            float sc  = scores[row];
            float ls  = fmaxf(logf(sc),    -100.0f);
            float l1  = fmaxf(log1pf(-sc), -100.0f);
            local += -(t * ls + (1.0f - t) * l1);
        }
    }

    if (lane == 0) s_red[wid] = local;
    __syncthreads();

    __shared__ unsigned int s_am_last;
    if (tid == 0) {
        float sum = 0.0f;
        #pragma unroll
        for (int i = 0; i < NWARPS; i++) sum += s_red[i];
        atomicAdd(&g_bce, (double)sum);
        __threadfence();                               // publish before ticket
        s_am_last = (atomicAdd(&g_ticket, 1u) == NBLK - 1);
    }
    __syncthreads();
    if (!s_am_last) return;

    // ---- Last block: all 512 BCE atomics are visible. Finalize. ----
    __threadfence();                                   // acquire side
    float ss = 0.0f;
    #pragma unroll
    for (int i = 0; i < (BB * DD) / NTHREADS; i++) {
        float v = __ldcg(&g_s[tid + i * NTHREADS]);
        ss += v * v;
    }
    #pragma unroll
    for (int o = 16; o > 0; o >>= 1)
        ss += __shfl_xor_sync(0xffffffffu, ss, o);
    if (lane == 0) s_red[wid] = ss;
    __syncthreads();
    if (wid == 0) {
        float t = (lane < NWARPS) ? s_red[lane] : 0.0f;
        #pragma unroll
        for (int o = 4; o > 0; o >>= 1)
            t += __shfl_xor_sync(0xffffffffu, t, o);
        if (lane == 0) {
            double bce       = atomicAdd(&g_bce, 0.0) / (double)(BB * NN);
            double mean_gram = (double)t /
                               ((double)BB * (double)NN * (double)NN);
            out[0] = (float)(bce + (1.0 - mean_gram));
            g_bce    = 0.0;                            // reset for next launch
            g_ticket = 0u;
        }
    }
    __syncthreads();                                   // all reads of g_s done
    #pragma unroll
    for (int i = 0; i < (BB * DD) / NTHREADS; i++)
        g_s[tid + i * NTHREADS] = 0.0f;                // reset for next launch
}

extern "C" void kernel_launch(void* const* d_in, const int* in_sizes, int n_in,
                              void* d_out, int out_size) {
    const float* feat   = (const float*)d_in[0];
    const float* scores = (const float*)d_in[1];
    float* out = (float*)d_out;

    pass1_kernel<<<NBLK, NTHREADS>>>(feat);
    pass2_kernel<<<NBLK, NTHREADS>>>(feat, scores, out);
}

// round 12
// speedup vs baseline: 1.3056x; 1.1093x over previous
#include <cuda_runtime.h>
#include <math.h>

// DistinctionLoss: two-kernel version, BCE tail decoupled from dot loop.
// features [8,4096,256] f32, scores [8,4096,1] f32 -> scalar f32.
//
// mean(gram) = sum_b ||s_b||^2 / (B*N^2), s_b = sum_n unit(features[b,n,:]).
// Kernel 1: per-row 1/norm + s_b accumulation (smem -> global atomics).
// Kernel 2: per-row dot vs s_b (streaming, RBATCH=4) -> fs to smem;
//           then 64-way-parallel BCE tail; last block (ticket) finalizes.

#define BB 8
#define NN 4096
#define DD 256
#define NBLK 512
#define NTHREADS 256
#define NWARPS (NTHREADS / 32)                   // 8
#define ROWS_PER_BLOCK ((BB * NN) / NBLK)        // 64
#define ROWS_PER_WARP  (ROWS_PER_BLOCK / NWARPS) // 8
#define RBATCH 4

// Persistent scratch; zero-initialized at module load, self-reset each launch.
__device__ float  g_rnorm[BB * NN];
__device__ float  g_s[BB * DD];
__device__ double g_bce;
__device__ unsigned int g_ticket;

// ---------------- Kernel 1: row norms + s_b accumulation ----------------
__global__ void __launch_bounds__(NTHREADS) pass1_kernel(const float* __restrict__ feat) {
    __shared__ float s_acc[DD];
    int tid  = threadIdx.x;
    int wid  = tid >> 5;
    int lane = tid & 31;
    s_acc[tid] = 0.0f;
    __syncthreads();

    int rowBase = blockIdx.x * ROWS_PER_BLOCK;   // 64 | 4096 -> single batch
    int b       = rowBase >> 12;
    int row0    = rowBase + wid * ROWS_PER_WARP;

    float4 acc0 = make_float4(0.f, 0.f, 0.f, 0.f);
    float4 acc1 = make_float4(0.f, 0.f, 0.f, 0.f);

    #pragma unroll
    for (int r = 0; r < ROWS_PER_WARP; r++) {
        int row = row0 + r;
        const float4* p = (const float4*)(feat + (size_t)row * DD);
        float4 v0 = p[lane];
        float4 v1 = p[lane + 32];
        float ss = v0.x*v0.x + v0.y*v0.y + v0.z*v0.z + v0.w*v0.w
                 + v1.x*v1.x + v1.y*v1.y + v1.z*v1.z + v1.w*v1.w;
        #pragma unroll
        for (int o = 16; o > 0; o >>= 1)
            ss += __shfl_xor_sync(0xffffffffu, ss, o);
        float rn = rsqrtf(fmaxf(ss, 1e-24f));
        if (lane == 0) g_rnorm[row] = rn;
        acc0.x += v0.x * rn; acc0.y += v0.y * rn;
        acc0.z += v0.z * rn; acc0.w += v0.w * rn;
        acc1.x += v1.x * rn; acc1.y += v1.y * rn;
        acc1.z += v1.z * rn; acc1.w += v1.w * rn;
    }

    int d0 = lane * 4;
    atomicAdd(&s_acc[d0 + 0],       acc0.x);
    atomicAdd(&s_acc[d0 + 1],       acc0.y);
    atomicAdd(&s_acc[d0 + 2],       acc0.z);
    atomicAdd(&s_acc[d0 + 3],       acc0.w);
    atomicAdd(&s_acc[128 + d0 + 0], acc1.x);
    atomicAdd(&s_acc[128 + d0 + 1], acc1.y);
    atomicAdd(&s_acc[128 + d0 + 2], acc1.z);
    atomicAdd(&s_acc[128 + d0 + 3], acc1.w);
    __syncthreads();

    atomicAdd(&g_s[b * DD + tid], s_acc[tid]);
}

// -------- Kernel 2: streaming dots -> parallel BCE tail -> finalize --------
__global__ void __launch_bounds__(NTHREADS) pass2_kernel(const float* __restrict__ feat,
                                                         const float* __restrict__ scores,
                                                         float* __restrict__ out) {
    __shared__ float s_fs[ROWS_PER_BLOCK];       // raw dot per row
    __shared__ float s_red[NWARPS];
    int tid  = threadIdx.x;
    int wid  = tid >> 5;
    int lane = tid & 31;

    int rowBase = blockIdx.x * ROWS_PER_BLOCK;
    int b       = rowBase >> 12;
    int row0    = rowBase + wid * ROWS_PER_WARP;

    // Lane-mapped s_b slices (atomics from pass1 landed in L2).
    const float4* gs4 = (const float4*)(g_s + b * DD);
    float4 s0 = __ldcg(&gs4[lane]);
    float4 s1 = __ldcg(&gs4[lane + 32]);

    // ---- Streaming dot loop: nothing on the critical path but loads+FMA+SHFL
    #pragma unroll
    for (int rb = 0; rb < ROWS_PER_WARP; rb += RBATCH) {
        float4 a0[RBATCH], a1[RBATCH];
        #pragma unroll
        for (int r = 0; r < RBATCH; r++) {        // 8 independent LDG.128
            const float4* p = (const float4*)(feat + (size_t)(row0 + rb + r) * DD);
            a0[r] = p[lane];
            a1[r] = p[lane + 32];
        }
        float dt[RBATCH];
        #pragma unroll
        for (int r = 0; r < RBATCH; r++)
            dt[r] = a0[r].x*s0.x + a0[r].y*s0.y + a0[r].z*s0.z + a0[r].w*s0.w
                  + a1[r].x*s1.x + a1[r].y*s1.y + a1[r].z*s1.z + a1[r].w*s1.w;
        #pragma unroll
        for (int o = 16; o > 0; o >>= 1) {        // 4 interleaved butterflies
            #pragma unroll
            for (int r = 0; r < RBATCH; r++)
                dt[r] += __shfl_xor_sync(0xffffffffu, dt[r], o);
        }
        if (lane == 0) {
            #pragma unroll
            for (int r = 0; r < RBATCH; r++)
                s_fs[wid * ROWS_PER_WARP + rb + r] = dt[r];
        }
    }
    __syncthreads();

    // ---- 64-way-parallel BCE tail (one thread per row) ----
    float local = 0.0f;
    if (tid < ROWS_PER_BLOCK) {
        int row   = rowBase + tid;
        float fs  = s_fs[tid] * g_rnorm[row];
        float sim = (fs - 1.0f) * (1.0f / (float)(NN - 1));
        float t   = 1.0f - fmaxf(sim, 0.0f);
        float sc  = scores[row];
        float ls  = fmaxf(__logf(sc),        -100.0f);
        float l1  = fmaxf(__logf(1.0f - sc), -100.0f);
        local = -(t * ls + (1.0f - t) * l1);
    }
    // reduce 64 values (warps 0,1)
    #pragma unroll
    for (int o = 16; o > 0; o >>= 1)
        local += __shfl_xor_sync(0xffffffffu, local, o);
    if (lane == 0) s_red[wid] = local;
    __syncthreads();

    __shared__ unsigned int s_am_last;
    if (tid == 0) {
        atomicAdd(&g_bce, (double)(s_red[0] + s_red[1]));
        __threadfence();                               // publish before ticket
        s_am_last = (atomicAdd(&g_ticket, 1u) == NBLK - 1);
    }
    __syncthreads();
    if (!s_am_last) return;

    // ---- Last block: all 512 BCE atomics are visible. Finalize. ----
    __threadfence();                                   // acquire side
    float ss = 0.0f;
    #pragma unroll
    for (int i = 0; i < (BB * DD) / NTHREADS; i++) {
        float v = __ldcg(&g_s[tid + i * NTHREADS]);
        ss += v * v;
    }
    #pragma unroll
    for (int o = 16; o > 0; o >>= 1)
        ss += __shfl_xor_sync(0xffffffffu, ss, o);
    if (lane == 0) s_red[wid] = ss;
    __syncthreads();
    if (wid == 0) {
        float t = (lane < NWARPS) ? s_red[lane] : 0.0f;
        #pragma unroll
        for (int o = 4; o > 0; o >>= 1)
            t += __shfl_xor_sync(0xffffffffu, t, o);
        if (lane == 0) {
            double bce       = atomicAdd(&g_bce, 0.0) / (double)(BB * NN);
            double mean_gram = (double)t /
                               ((double)BB * (double)NN * (double)NN);
            out[0] = (float)(bce + (1.0 - mean_gram));
            g_bce    = 0.0;                            // reset for next launch
            g_ticket = 0u;
        }
    }
    __syncthreads();                                   // all reads of g_s done
    #pragma unroll
    for (int i = 0; i < (BB * DD) / NTHREADS; i++)
        g_s[tid + i * NTHREADS] = 0.0f;                // reset for next launch
}

extern "C" void kernel_launch(void* const* d_in, const int* in_sizes, int n_in,
                              void* d_out, int out_size) {
    const float* feat   = (const float*)d_in[0];
    const float* scores = (const float*)d_in[1];
    float* out = (float*)d_out;

    pass1_kernel<<<NBLK, NTHREADS>>>(feat);
    pass2_kernel<<<NBLK, NTHREADS>>>(feat, scores, out);
}